// round 15
// baseline (speedup 1.0000x reference)
#include <cuda_runtime.h>
#include <cuda_fp16.h>
#include <cstdint>

#define DEV_INLINE __device__ __forceinline__

constexpr int Bsz = 16, Pseq = 1024, E = 1024, H = 16, D = 64;
constexpr int M = Bsz * Pseq;   // 16384 rows
constexpr int K = E;            // 1024
constexpr int N = E;            // 1024

// log2(e)/sqrt(P) = 1.4426950408889634/32, folded into Q projection
constexpr float SCf = 0.045084220027780106f;

// Scratch (static device allocations; no cudaMalloc allowed)
__device__ __half g_xh [(size_t)M * E];      // x in fp16 [M,E]
__device__ __half g_w4 [(size_t)4 * E * E];  // wq|wk|wv|wo in fp16 [4][N,K]
__device__ __half g_q  [(size_t)M * E];      // [B,H,P,D] (pre-scaled by SCf)
__device__ __half g_k  [(size_t)M * E];      // [B,H,P,D]
__device__ __half g_vt [(size_t)M * E];      // [B,H,D,P]  (V transposed)
__device__ __half g_ctx[(size_t)M * E];      // [B,P,H*D] == [M,E]

DEV_INLINE void mma16816(float* c, const uint32_t* a, const uint32_t* b) {
    asm volatile(
        "mma.sync.aligned.m16n8k16.row.col.f32.f16.f16.f32 "
        "{%0,%1,%2,%3}, {%4,%5,%6,%7}, {%8,%9}, {%0,%1,%2,%3};\n"
        : "+f"(c[0]), "+f"(c[1]), "+f"(c[2]), "+f"(c[3])
        : "r"(a[0]), "r"(a[1]), "r"(a[2]), "r"(a[3]), "r"(b[0]), "r"(b[1]));
}

DEV_INLINE uint32_t smem_u32(const void* p) {
    uint32_t a;
    asm("{ .reg .u64 t; cvta.to.shared.u64 t, %1; cvt.u32.u64 %0, t; }"
        : "=r"(a) : "l"(p));
    return a;
}

DEV_INLINE void ldsm_x4(uint32_t& r0, uint32_t& r1, uint32_t& r2, uint32_t& r3,
                        uint32_t addr) {
    asm volatile(
        "ldmatrix.sync.aligned.m8n8.x4.shared.b16 {%0, %1, %2, %3}, [%4];"
        : "=r"(r0), "=r"(r1), "=r"(r2), "=r"(r3) : "r"(addr));
}

DEV_INLINE void cp16(uint32_t smem_addr, const void* gptr) {
    asm volatile("cp.async.cg.shared.global [%0], [%1], 16;"
                 :: "r"(smem_addr), "l"(gptr));
}
DEV_INLINE void cp_commit() { asm volatile("cp.async.commit_group;"); }
template<int Nn> DEV_INLINE void cp_wait() {
    asm volatile("cp.async.wait_group %0;" :: "n"(Nn));
}

DEV_INLINE uint32_t pack_h2(float lo, float hi) {
    __half2 h = __floats2half2_rn(lo, hi);
    return *reinterpret_cast<uint32_t*>(&h);
}

DEV_INLINE uint32_t h2exp2(uint32_t x) {     // ex2 on both fp16 halves
    uint32_t y;
    asm("ex2.approx.f16x2 %0, %1;" : "=r"(y) : "r"(x));
    return y;
}

// ---------------------------------------------------------------------------
// fp32 -> fp16 conversion kernels
// ---------------------------------------------------------------------------
__global__ void cvt_kernel(const float* __restrict__ src, __half* __restrict__ dst,
                           int n4)
{
    int i = blockIdx.x * blockDim.x + threadIdx.x;
    int stride = gridDim.x * blockDim.x;
    for (; i < n4; i += stride) {
        float4 f = *(const float4*)(src + (size_t)i * 4);
        uint2 u;
        u.x = pack_h2(f.x, f.y);
        u.y = pack_h2(f.z, f.w);
        *(uint2*)(dst + (size_t)i * 4) = u;
    }
}

__global__ void wcvt_kernel(const float* __restrict__ w0, const float* __restrict__ w1,
                            const float* __restrict__ w2, const float* __restrict__ w3,
                            __half* __restrict__ dst)
{
    const int z = blockIdx.y;
    const float* src = (z == 0) ? w0 : (z == 1) ? w1 : (z == 2) ? w2 : w3;
    __half* d = dst + (size_t)z * E * E;
    const int n4 = E * E / 4;
    int i = blockIdx.x * blockDim.x + threadIdx.x;
    int stride = gridDim.x * blockDim.x;
    for (; i < n4; i += stride) {
        float4 f = *(const float4*)(src + (size_t)i * 4);
        uint2 u;
        u.x = pack_h2(f.x, f.y);
        u.y = pack_h2(f.z, f.w);
        *(uint2*)(d + (size_t)i * 4) = u;
    }
}

// ---------------------------------------------------------------------------
// GEMM core: BK=128 (8 barrier intervals per K=1024, was 16), 2-stage
// cp.async, 256 threads, 2x4 warp grid (64x32 warp tile, R9-proven mapping).
// 1 CTA/SM (136 KB smem) = 8 warps, 2/SMSP.
// ---------------------------------------------------------------------------
constexpr int BM = 128, BN = 128, BK = 128, LDSMs = BK + 8;  // 136-half stride
constexpr int HALF_TILE_B = BM * LDSMs * 2;                  // 34816 bytes
constexpr int STAGE_B = 2 * HALF_TILE_B;                     // 69632 bytes
constexpr int STAGES = 2;
constexpr int GEMM_SMEM = STAGES * STAGE_B;                  // 139264 bytes

DEV_INLINE void gemm_core(const __half* __restrict__ A,
                          const __half* __restrict__ Wp,
                          int tileM, int tileN, char* sm,
                          float acc[4][4][4])
{
    const int tid = threadIdx.x, warp = tid >> 5, lane = tid & 31;
    const int wm = warp >> 2, wn = warp & 3;     // 2 x 4 warp grid
    const int l8 = lane & 7;
    const int aRowOff = ((lane >> 3) & 1) * 8;
    const int aColOff = ((lane >> 4) & 1) * 8;
    const int bRowOff = ((lane >> 4) & 1) * 8;
    const int bColOff = ((lane >> 3) & 1) * 8;

    #pragma unroll
    for (int i = 0; i < 4; i++)
        #pragma unroll
        for (int j = 0; j < 4; j++)
            #pragma unroll
            for (int r = 0; r < 4; r++) acc[i][j][r] = 0.f;

    const uint32_t smb = smem_u32(sm);

    uint32_t aOff[4], bOff[2];
    #pragma unroll
    for (int mf = 0; mf < 4; mf++) {
        int row = wm * 64 + mf * 16 + aRowOff + l8;
        aOff[mf] = (uint32_t)(row * LDSMs + aColOff) * 2;
    }
    #pragma unroll
    for (int np = 0; np < 2; np++) {
        int row = wn * 32 + np * 16 + bRowOff + l8;
        bOff[np] = (uint32_t)(row * LDSMs + bColOff) * 2 + HALF_TILE_B;
    }

    // Copy slice: 128 rows x 16 chunks(16B) per matrix = 2048 slots, 256 thr
    auto issue = [&](int kt, int s) {
        const uint32_t sa = smb + s * STAGE_B;
        #pragma unroll
        for (int i = 0; i < 8; i++) {
            int idx = tid + 256 * i;
            int row = idx >> 4, grp = idx & 15;
            uint32_t soff = (uint32_t)(row * LDSMs + grp * 8) * 2;
            cp16(sa + soff,
                 A + (size_t)(tileM + row) * K + kt * BK + grp * 8);
            cp16(sa + HALF_TILE_B + soff,
                 Wp + (size_t)(tileN + row) * K + kt * BK + grp * 8);
        }
    };

    auto compute = [&](int s) {
        const uint32_t sa = smb + s * STAGE_B;
        #pragma unroll
        for (int ks = 0; ks < 8; ks++) {
            const uint32_t kbB = (uint32_t)(ks * 32);   // 16 halves = 32 bytes
            uint32_t af[4][4], bf[4][2];
            #pragma unroll
            for (int mf = 0; mf < 4; mf++)
                ldsm_x4(af[mf][0], af[mf][1], af[mf][2], af[mf][3],
                        sa + aOff[mf] + kbB);
            #pragma unroll
            for (int np = 0; np < 2; np++)
                ldsm_x4(bf[2 * np][0], bf[2 * np][1],
                        bf[2 * np + 1][0], bf[2 * np + 1][1],
                        sa + bOff[np] + kbB);
            #pragma unroll
            for (int mf = 0; mf < 4; mf++)
                #pragma unroll
                for (int nf = 0; nf < 4; nf++)
                    mma16816(acc[mf][nf], af[mf], bf[nf]);
        }
    };

    constexpr int NT = K / BK;      // 8 tiles
    issue(0, 0); cp_commit();
    for (int kt = 0; kt < NT; kt++) {
        cp_wait<0>();               // tile kt landed
        __syncthreads();            // all warps done reading buffer (kt+1)&1
        if (kt + 1 < NT) issue(kt + 1, (kt + 1) & 1);
        cp_commit();                // uniform group count (empty ok)
        compute(kt & 1);            // overlaps with kt+1's copy
    }
}

// ---------------------------------------------------------------------------
// Fused QKV GEMM: z=0 -> q (pre-scaled by SCf), z=1 -> k, z=2 -> v transposed
// ---------------------------------------------------------------------------
__global__ __launch_bounds__(256, 1) void qkv_gemm(
    const __half* __restrict__ Xh, const __half* __restrict__ Wall,
    const float* __restrict__ bq, const float* __restrict__ bk,
    const float* __restrict__ bv,
    __half* __restrict__ outq, __half* __restrict__ outk,
    __half* __restrict__ outvt)
{
    extern __shared__ __align__(16) char sm[];
    const int z = blockIdx.z;
    const __half* Wp = Wall + (size_t)z * E * E;
    const float* bias = (z == 0) ? bq : (z == 1) ? bk : bv;
    __half* Out = (z == 0) ? outq : (z == 1) ? outk : outvt;
    const int tileM = blockIdx.x * BM, tileN = blockIdx.y * BN;
    const float sc = (z == 0) ? SCf : 1.0f;

    float acc[4][4][4];
    gemm_core(Xh, Wp, tileM, tileN, sm, acc);

    const int warp = threadIdx.x >> 5, lane = threadIdx.x & 31;
    const int wm = warp >> 2, wn = warp & 3;
    #pragma unroll
    for (int mf = 0; mf < 4; mf++) {
        #pragma unroll
        for (int nf = 0; nf < 4; nf++) {
            int m0 = tileM + wm * 64 + mf * 16 + (lane >> 2);
            int n0 = tileN + wn * 32 + nf * 8 + (lane & 3) * 2;
            float bv0 = bias[n0], bv1 = bias[n0 + 1];
            float v00 = (acc[mf][nf][0] + bv0) * sc, v01 = (acc[mf][nf][1] + bv1) * sc;
            float v10 = (acc[mf][nf][2] + bv0) * sc, v11 = (acc[mf][nf][3] + bv1) * sc;
            int b0 = m0 >> 10, p0 = m0 & 1023;
            int h0 = n0 >> 6,  d0 = n0 & 63;
            if (z < 2) {       // [B,H,P,D]
                size_t base = (size_t)(b0 * H + h0) * Pseq * D;
                *(__half2*)(Out + base + (size_t)p0 * D + d0)       = __floats2half2_rn(v00, v01);
                *(__half2*)(Out + base + (size_t)(p0 + 8) * D + d0) = __floats2half2_rn(v10, v11);
            } else {           // [B,H,D,P]
                size_t base = (size_t)(b0 * H + h0) * D * Pseq;
                Out[base + (size_t)d0 * Pseq + p0]           = __float2half_rn(v00);
                Out[base + (size_t)(d0 + 1) * Pseq + p0]     = __float2half_rn(v01);
                Out[base + (size_t)d0 * Pseq + p0 + 8]       = __float2half_rn(v10);
                Out[base + (size_t)(d0 + 1) * Pseq + p0 + 8] = __float2half_rn(v11);
            }
        }
    }
}

// ---------------------------------------------------------------------------
// Output GEMM: ctx(fp16) @ wo^T + bo -> fp32 [M,N]
// ---------------------------------------------------------------------------
__global__ __launch_bounds__(256, 1) void o_gemm(
    const __half* __restrict__ Ctx, const __half* __restrict__ Wo,
    const float* __restrict__ bias, float* __restrict__ Out)
{
    extern __shared__ __align__(16) char sm[];
    const int tileM = blockIdx.x * BM, tileN = blockIdx.y * BN;

    float acc[4][4][4];
    gemm_core(Ctx, Wo, tileM, tileN, sm, acc);

    const int warp = threadIdx.x >> 5, lane = threadIdx.x & 31;
    const int wm = warp >> 2, wn = warp & 3;
    #pragma unroll
    for (int mf = 0; mf < 4; mf++) {
        #pragma unroll
        for (int nf = 0; nf < 4; nf++) {
            int m0 = tileM + wm * 64 + mf * 16 + (lane >> 2);
            int n0 = tileN + wn * 32 + nf * 8 + (lane & 3) * 2;
            float bv0 = bias[n0], bv1 = bias[n0 + 1];
            *(float2*)(Out + (size_t)m0 * N + n0) =
                make_float2(acc[mf][nf][0] + bv0, acc[mf][nf][1] + bv1);
            *(float2*)(Out + (size_t)(m0 + 8) * N + n0) =
                make_float2(acc[mf][nf][2] + bv0, acc[mf][nf][3] + bv1);
        }
    }
}

// ---------------------------------------------------------------------------
// Attention (unchanged from R13): 128 threads, 4 warps x 32 q-rows.
// fp16x2 exp2, ones-row row sums via tensor pipe.
// ---------------------------------------------------------------------------
__global__ __launch_bounds__(128, 2) void attn_kernel(
    const __half* __restrict__ Q, const __half* __restrict__ Kg,
    const __half* __restrict__ Vt, __half* __restrict__ Ctx)
{
    constexpr int LDSA = 72;               // 144B stride: ldmatrix conflict-free
    constexpr int KV_STAGE_B = 64 * LDSA * 2;    // K buffer: 9216 bytes
    constexpr int V_STAGE_B  = 80 * LDSA * 2;    // V buffer incl. ones rows
    __shared__ __align__(16) __half Ks[2][64 * LDSA];   // [key][d]
    __shared__ __align__(16) __half Vs[2][80 * LDSA];   // [d][key] + ones block

    const int tid = threadIdx.x, warp = tid >> 5, lane = tid & 31;
    const int bh = blockIdx.y;
    const int qbase = blockIdx.x * 128;
    const int c0 = (lane & 3) * 2;
    const int l8 = lane & 7;
    const int bRowOff = ((lane >> 4) & 1) * 8;
    const int bColOff = ((lane >> 3) & 1) * 8;
    const __half* Qb = Q  + (size_t)bh * Pseq * D;
    const __half* Kb = Kg + (size_t)bh * Pseq * D;
    const __half* Vb = Vt + (size_t)bh * D * Pseq;

    // Q fragments: 2 m-frags x 4 k-steps
    uint32_t qf[2][4][4];
    #pragma unroll
    for (int mf = 0; mf < 2; mf++) {
        int r0 = qbase + warp * 32 + mf * 16 + (lane >> 2);
        #pragma unroll
        for (int ks = 0; ks < 4; ks++) {
            qf[mf][ks][0] = *(const uint32_t*)(Qb + (size_t)r0 * D + ks * 16 + c0);
            qf[mf][ks][1] = *(const uint32_t*)(Qb + (size_t)(r0 + 8) * D + ks * 16 + c0);
            qf[mf][ks][2] = *(const uint32_t*)(Qb + (size_t)r0 * D + ks * 16 + c0 + 8);
            qf[mf][ks][3] = *(const uint32_t*)(Qb + (size_t)(r0 + 8) * D + ks * 16 + c0 + 8);
        }
    }

    const uint32_t ksBase = smem_u32(&Ks[0][0]);
    const uint32_t vsBase = smem_u32(&Vs[0][0]);
    uint32_t rOff[5];
    #pragma unroll
    for (int np = 0; np < 5; np++) {
        int row = np * 16 + bRowOff + l8;
        rOff[np] = (uint32_t)(row * LDSA + bColOff) * 2;
    }

    // Ones-row blocks in both V buffers (cp.async only writes rows 0..63)
    for (int idx = tid; idx < 16 * 64; idx += 128) {
        int r = idx >> 6, c = idx & 63;
        __half v = (r == 0) ? __float2half(1.0f) : __float2half(0.0f);
        Vs[0][(64 + r) * LDSA + c] = v;
        Vs[1][(64 + r) * LDSA + c] = v;
    }

    float o[2][8][4];
    #pragma unroll
    for (int mf = 0; mf < 2; mf++)
        #pragma unroll
        for (int i = 0; i < 8; i++)
            #pragma unroll
            for (int r = 0; r < 4; r++) o[mf][i][r] = 0.f;
    float o9[2][4] = {};

    auto issueKV = [&](int kt, int s) {
        #pragma unroll
        for (int i = 0; i < 4; i++) {
            int idx = tid + 128 * i;
            int row = idx >> 3, grp = idx & 7;
            cp16(ksBase + (uint32_t)(row * LDSA + grp * 8) * 2 + s * KV_STAGE_B,
                 Kb + (size_t)(kt * 64 + row) * D + grp * 8);
            cp16(vsBase + (uint32_t)(row * LDSA + grp * 8) * 2 + s * V_STAGE_B,
                 Vb + (size_t)row * Pseq + kt * 64 + grp * 8);
        }
    };

    issueKV(0, 0); cp_commit();
    __syncthreads();           // ones-block init visible before first compute
    for (int kt = 0; kt < 16; kt++) {
        const int s = kt & 1;
        const uint32_t kBuf = ksBase + s * KV_STAGE_B;
        const uint32_t vBuf = vsBase + s * V_STAGE_B;
        cp_wait<0>();
        __syncthreads();
        if (kt < 15) issueKV(kt + 1, s ^ 1);
        cp_commit();

        // S = Q K^T  (32 x 64 per warp); each bf load feeds both m-frags
        float sreg[2][8][4];
        #pragma unroll
        for (int mf = 0; mf < 2; mf++)
            #pragma unroll
            for (int i = 0; i < 8; i++)
                #pragma unroll
                for (int r = 0; r < 4; r++) sreg[mf][i][r] = 0.f;
        #pragma unroll
        for (int ks = 0; ks < 4; ks++) {
            uint32_t bf[8][2];
            #pragma unroll
            for (int np = 0; np < 4; np++)
                ldsm_x4(bf[2 * np][0], bf[2 * np][1],
                        bf[2 * np + 1][0], bf[2 * np + 1][1],
                        kBuf + rOff[np] + ks * 32);
            #pragma unroll
            for (int mf = 0; mf < 2; mf++)
                #pragma unroll
                for (int nf = 0; nf < 8; nf++)
                    mma16816(sreg[mf][nf], qf[mf][ks], bf[nf]);
        }

        // softmax numerator: pack to PV A-frag layout, then fp16x2 exp2
        uint32_t pf[2][4][4];
        #pragma unroll
        for (int mf = 0; mf < 2; mf++)
            #pragma unroll
            for (int jj = 0; jj < 4; jj++) {
                pf[mf][jj][0] = h2exp2(pack_h2(sreg[mf][2 * jj][0],     sreg[mf][2 * jj][1]));
                pf[mf][jj][1] = h2exp2(pack_h2(sreg[mf][2 * jj][2],     sreg[mf][2 * jj][3]));
                pf[mf][jj][2] = h2exp2(pack_h2(sreg[mf][2 * jj + 1][0], sreg[mf][2 * jj + 1][1]));
                pf[mf][jj][3] = h2exp2(pack_h2(sreg[mf][2 * jj + 1][2], sreg[mf][2 * jj + 1][3]));
            }

        // O += P V ; 9th n-frag (ones row) accumulates row sums
        #pragma unroll
        for (int jj = 0; jj < 4; jj++) {
            uint32_t bf[8][2], b9[4];
            #pragma unroll
            for (int np = 0; np < 4; np++)
                ldsm_x4(bf[2 * np][0], bf[2 * np][1],
                        bf[2 * np + 1][0], bf[2 * np + 1][1],
                        vBuf + rOff[np] + jj * 32);
            ldsm_x4(b9[0], b9[1], b9[2], b9[3], vBuf + rOff[4] + jj * 32);
            #pragma unroll
            for (int mf = 0; mf < 2; mf++) {
                #pragma unroll
                for (int nf = 0; nf < 8; nf++)
                    mma16816(o[mf][nf], pf[mf][jj], bf[nf]);
                mma16816(o9[mf], pf[mf][jj], b9);
            }
        }
    }

    const int b0 = bh >> 4, h0 = bh & 15;
    const size_t obase = (size_t)b0 * Pseq * E + (size_t)h0 * D;
    #pragma unroll
    for (int mf = 0; mf < 2; mf++) {
        const float rin0 = 1.f / __shfl_sync(0xffffffffu, o9[mf][0], 0, 4);
        const float rin1 = 1.f / __shfl_sync(0xffffffffu, o9[mf][2], 0, 4);
        const int prow = qbase + warp * 32 + mf * 16 + (lane >> 2);
        #pragma unroll
        for (int nf = 0; nf < 8; nf++) {
            int d0 = nf * 8 + c0;
            *(__half2*)(Ctx + obase + (size_t)prow * E + d0) =
                __floats2half2_rn(o[mf][nf][0] * rin0, o[mf][nf][1] * rin0);
            *(__half2*)(Ctx + obase + (size_t)(prow + 8) * E + d0) =
                __floats2half2_rn(o[mf][nf][2] * rin1, o[mf][nf][3] * rin1);
        }
    }
}

// ---------------------------------------------------------------------------
extern "C" void kernel_launch(void* const* d_in, const int* in_sizes, int n_in,
                              void* d_out, int out_size)
{
    const float* x  = (const float*)d_in[0];
    const float* wq = (const float*)d_in[1];
    const float* bq = (const float*)d_in[2];
    const float* wk = (const float*)d_in[3];
    const float* bk = (const float*)d_in[4];
    const float* wv = (const float*)d_in[5];
    const float* bv = (const float*)d_in[6];
    const float* wo = (const float*)d_in[7];
    const float* bo = (const float*)d_in[8];

    void *pxh, *pw4, *pq, *pk, *pv, *pc;
    cudaGetSymbolAddress(&pxh, g_xh);
    cudaGetSymbolAddress(&pw4, g_w4);
    cudaGetSymbolAddress(&pq, g_q);
    cudaGetSymbolAddress(&pk, g_k);
    cudaGetSymbolAddress(&pv, g_vt);
    cudaGetSymbolAddress(&pc, g_ctx);

    __half* xh = (__half*)pxh;
    __half* w4 = (__half*)pw4;

    cudaFuncSetAttribute(qkv_gemm, cudaFuncAttributeMaxDynamicSharedMemorySize,
                         GEMM_SMEM);
    cudaFuncSetAttribute(o_gemm, cudaFuncAttributeMaxDynamicSharedMemorySize,
                         GEMM_SMEM);

    // Pre-convert inputs to fp16
    cvt_kernel<<<1024, 256>>>(x, xh, M * E / 4);
    wcvt_kernel<<<dim3(128, 4), 256>>>(wq, wk, wv, wo, w4);

    dim3 gq(M / BM, N / BN, 3);
    qkv_gemm<<<gq, 256, GEMM_SMEM>>>(xh, w4, bq, bk, bv,
                                     (__half*)pq, (__half*)pk, (__half*)pv);
    attn_kernel<<<dim3(8, 256), 128>>>((const __half*)pq, (const __half*)pk,
                                       (const __half*)pv, (__half*)pc);
    o_gemm<<<dim3(M / BM, N / BN), 256, GEMM_SMEM>>>((const __half*)pc,
                                                     w4 + 3 * (size_t)E * E, bo,
                                                     (float*)d_out);
}

// round 16
// speedup vs baseline: 1.1444x; 1.1444x over previous
#include <cuda_runtime.h>
#include <cuda_fp16.h>
#include <cstdint>

#define DEV_INLINE __device__ __forceinline__

constexpr int Bsz = 16, Pseq = 1024, E = 1024, H = 16, D = 64;
constexpr int M = Bsz * Pseq;   // 16384 rows
constexpr int K = E;            // 1024
constexpr int N = E;            // 1024

// log2(e)/sqrt(P) = 1.4426950408889634/32, folded into Q projection
constexpr float SCf = 0.045084220027780106f;

// Scratch (static device allocations; no cudaMalloc allowed)
__device__ __half g_xh [(size_t)M * E];      // x in fp16 [M,E]
__device__ __half g_w4 [(size_t)4 * E * E];  // wq|wk|wv|wo in fp16 [4][N,K]
__device__ __half g_q  [(size_t)M * E];      // [B,H,P,D] (pre-scaled by SCf)
__device__ __half g_k  [(size_t)M * E];      // [B,H,P,D]
__device__ __half g_vt [(size_t)M * E];      // [B,H,D,P]  (V transposed)
__device__ __half g_ctx[(size_t)M * E];      // [B,P,H*D] == [M,E]

DEV_INLINE void mma16816(float* c, const uint32_t* a, const uint32_t* b) {
    asm volatile(
        "mma.sync.aligned.m16n8k16.row.col.f32.f16.f16.f32 "
        "{%0,%1,%2,%3}, {%4,%5,%6,%7}, {%8,%9}, {%0,%1,%2,%3};\n"
        : "+f"(c[0]), "+f"(c[1]), "+f"(c[2]), "+f"(c[3])
        : "r"(a[0]), "r"(a[1]), "r"(a[2]), "r"(a[3]), "r"(b[0]), "r"(b[1]));
}

DEV_INLINE uint32_t smem_u32(const void* p) {
    uint32_t a;
    asm("{ .reg .u64 t; cvta.to.shared.u64 t, %1; cvt.u32.u64 %0, t; }"
        : "=r"(a) : "l"(p));
    return a;
}

DEV_INLINE void ldsm_x4(uint32_t& r0, uint32_t& r1, uint32_t& r2, uint32_t& r3,
                        uint32_t addr) {
    asm volatile(
        "ldmatrix.sync.aligned.m8n8.x4.shared.b16 {%0, %1, %2, %3}, [%4];"
        : "=r"(r0), "=r"(r1), "=r"(r2), "=r"(r3) : "r"(addr));
}

DEV_INLINE void cp16(uint32_t smem_addr, const void* gptr) {
    asm volatile("cp.async.cg.shared.global [%0], [%1], 16;"
                 :: "r"(smem_addr), "l"(gptr));
}
DEV_INLINE void cp_commit() { asm volatile("cp.async.commit_group;"); }
template<int Nn> DEV_INLINE void cp_wait() {
    asm volatile("cp.async.wait_group %0;" :: "n"(Nn));
}

DEV_INLINE uint32_t pack_h2(float lo, float hi) {
    __half2 h = __floats2half2_rn(lo, hi);
    return *reinterpret_cast<uint32_t*>(&h);
}

DEV_INLINE uint32_t h2exp2(uint32_t x) {     // ex2 on both fp16 halves
    uint32_t y;
    asm("ex2.approx.f16x2 %0, %1;" : "=r"(y) : "r"(x));
    return y;
}

// ---------------------------------------------------------------------------
// fp32 -> fp16 conversion kernels
// ---------------------------------------------------------------------------
__global__ void cvt_kernel(const float* __restrict__ src, __half* __restrict__ dst,
                           int n4)
{
    int i = blockIdx.x * blockDim.x + threadIdx.x;
    int stride = gridDim.x * blockDim.x;
    for (; i < n4; i += stride) {
        float4 f = *(const float4*)(src + (size_t)i * 4);
        uint2 u;
        u.x = pack_h2(f.x, f.y);
        u.y = pack_h2(f.z, f.w);
        *(uint2*)(dst + (size_t)i * 4) = u;
    }
}

__global__ void wcvt_kernel(const float* __restrict__ w0, const float* __restrict__ w1,
                            const float* __restrict__ w2, const float* __restrict__ w3,
                            __half* __restrict__ dst)
{
    const int z = blockIdx.y;
    const float* src = (z == 0) ? w0 : (z == 1) ? w1 : (z == 2) ? w2 : w3;
    __half* d = dst + (size_t)z * E * E;
    const int n4 = E * E / 4;
    int i = blockIdx.x * blockDim.x + threadIdx.x;
    int stride = gridDim.x * blockDim.x;
    for (; i < n4; i += stride) {
        float4 f = *(const float4*)(src + (size_t)i * 4);
        uint2 u;
        u.x = pack_h2(f.x, f.y);
        u.y = pack_h2(f.z, f.w);
        *(uint2*)(d + (size_t)i * 4) = u;
    }
}

// ---------------------------------------------------------------------------
// GEMM core (R9/R13-proven): BK=64, 3-stage cp.async pipeline, 128x128 tile,
// 256 threads, 2x4 warp grid, ldmatrix feeds, hoisted fragment addresses.
// ---------------------------------------------------------------------------
constexpr int BM = 128, BN = 128, BK = 64, LDSMs = BK + 8;   // 72-half stride
constexpr int HALF_TILE_B = BM * LDSMs * 2;                  // 18432 bytes
constexpr int STAGE_B = 2 * HALF_TILE_B;                     // 36864 bytes
constexpr int STAGES = 3;
constexpr int GEMM_SMEM = STAGES * STAGE_B;                  // 110592 bytes

DEV_INLINE void gemm_core(const __half* __restrict__ A,
                          const __half* __restrict__ Wp,
                          int tileM, int tileN, char* sm,
                          float acc[4][4][4])
{
    const int tid = threadIdx.x, warp = tid >> 5, lane = tid & 31;
    const int wm = warp >> 2, wn = warp & 3;
    const int l8 = lane & 7;
    const int aRowOff = ((lane >> 3) & 1) * 8;
    const int aColOff = ((lane >> 4) & 1) * 8;
    const int bRowOff = ((lane >> 4) & 1) * 8;
    const int bColOff = ((lane >> 3) & 1) * 8;

    #pragma unroll
    for (int i = 0; i < 4; i++)
        #pragma unroll
        for (int j = 0; j < 4; j++)
            #pragma unroll
            for (int r = 0; r < 4; r++) acc[i][j][r] = 0.f;

    const uint32_t smb = smem_u32(sm);

    uint32_t aOff[4], bOff[2];
    #pragma unroll
    for (int mf = 0; mf < 4; mf++) {
        int row = wm * 64 + mf * 16 + aRowOff + l8;
        aOff[mf] = (uint32_t)(row * LDSMs + aColOff) * 2;
    }
    #pragma unroll
    for (int np = 0; np < 2; np++) {
        int row = wn * 32 + np * 16 + bRowOff + l8;
        bOff[np] = (uint32_t)(row * LDSMs + bColOff) * 2 + HALF_TILE_B;
    }

    auto issue = [&](int kt, int s) {
        const uint32_t sa = smb + s * STAGE_B;
        #pragma unroll
        for (int i = 0; i < 4; i++) {
            int idx = tid + 256 * i;
            int row = idx >> 3, grp = idx & 7;
            uint32_t soff = (uint32_t)(row * LDSMs + grp * 8) * 2;
            cp16(sa + soff,
                 A + (size_t)(tileM + row) * K + kt * BK + grp * 8);
            cp16(sa + HALF_TILE_B + soff,
                 Wp + (size_t)(tileN + row) * K + kt * BK + grp * 8);
        }
    };

    auto compute = [&](int s) {
        const uint32_t sa = smb + s * STAGE_B;
        #pragma unroll
        for (int ks = 0; ks < 4; ks++) {
            const uint32_t kbB = (uint32_t)(ks * 32);
            uint32_t af[4][4], bf[4][2];
            #pragma unroll
            for (int mf = 0; mf < 4; mf++)
                ldsm_x4(af[mf][0], af[mf][1], af[mf][2], af[mf][3],
                        sa + aOff[mf] + kbB);
            #pragma unroll
            for (int np = 0; np < 2; np++)
                ldsm_x4(bf[2 * np][0], bf[2 * np][1],
                        bf[2 * np + 1][0], bf[2 * np + 1][1],
                        sa + bOff[np] + kbB);
            #pragma unroll
            for (int mf = 0; mf < 4; mf++)
                #pragma unroll
                for (int nf = 0; nf < 4; nf++)
                    mma16816(acc[mf][nf], af[mf], bf[nf]);
        }
    };

    constexpr int NT = K / BK;      // 16 tiles
    issue(0, 0); cp_commit();
    issue(1, 1); cp_commit();
    for (int kt = 0; kt < NT; kt++) {
        cp_wait<1>();
        __syncthreads();
        if (kt + 2 < NT) issue(kt + 2, (kt + 2) % 3);
        cp_commit();
        compute(kt % 3);
    }
}

// ---------------------------------------------------------------------------
// Fused QKV GEMM. Grid: (x = N-tiles = 8, y = M-tiles = 128, z = 0..2).
// x-fast launch order makes a resident wave span all N-tiles of ~37 M-tiles:
// each A tile is read once from HBM and reused 8x from L2 (was: every wave
// re-streamed the whole 32 MB A matrix).
// ---------------------------------------------------------------------------
__global__ __launch_bounds__(256, 2) void qkv_gemm(
    const __half* __restrict__ Xh, const __half* __restrict__ Wall,
    const float* __restrict__ bq, const float* __restrict__ bk,
    const float* __restrict__ bv,
    __half* __restrict__ outq, __half* __restrict__ outk,
    __half* __restrict__ outvt)
{
    extern __shared__ __align__(16) char sm[];
    const int z = blockIdx.z;
    const __half* Wp = Wall + (size_t)z * E * E;
    const float* bias = (z == 0) ? bq : (z == 1) ? bk : bv;
    __half* Out = (z == 0) ? outq : (z == 1) ? outk : outvt;
    const int tileM = blockIdx.y * BM, tileN = blockIdx.x * BN;   // swapped
    const float sc = (z == 0) ? SCf : 1.0f;

    float acc[4][4][4];
    gemm_core(Xh, Wp, tileM, tileN, sm, acc);

    const int warp = threadIdx.x >> 5, lane = threadIdx.x & 31;
    const int wm = warp >> 2, wn = warp & 3;
    #pragma unroll
    for (int mf = 0; mf < 4; mf++) {
        #pragma unroll
        for (int nf = 0; nf < 4; nf++) {
            int m0 = tileM + wm * 64 + mf * 16 + (lane >> 2);
            int n0 = tileN + wn * 32 + nf * 8 + (lane & 3) * 2;
            float bv0 = bias[n0], bv1 = bias[n0 + 1];
            float v00 = (acc[mf][nf][0] + bv0) * sc, v01 = (acc[mf][nf][1] + bv1) * sc;
            float v10 = (acc[mf][nf][2] + bv0) * sc, v11 = (acc[mf][nf][3] + bv1) * sc;
            int b0 = m0 >> 10, p0 = m0 & 1023;
            int h0 = n0 >> 6,  d0 = n0 & 63;
            if (z < 2) {       // [B,H,P,D]
                size_t base = (size_t)(b0 * H + h0) * Pseq * D;
                *(__half2*)(Out + base + (size_t)p0 * D + d0)       = __floats2half2_rn(v00, v01);
                *(__half2*)(Out + base + (size_t)(p0 + 8) * D + d0) = __floats2half2_rn(v10, v11);
            } else {           // [B,H,D,P]
                size_t base = (size_t)(b0 * H + h0) * D * Pseq;
                Out[base + (size_t)d0 * Pseq + p0]           = __float2half_rn(v00);
                Out[base + (size_t)(d0 + 1) * Pseq + p0]     = __float2half_rn(v01);
                Out[base + (size_t)d0 * Pseq + p0 + 8]       = __float2half_rn(v10);
                Out[base + (size_t)(d0 + 1) * Pseq + p0 + 8] = __float2half_rn(v11);
            }
        }
    }
}

// ---------------------------------------------------------------------------
// Output GEMM: ctx(fp16) @ wo^T + bo -> fp32 [M,N]. Same swapped grid.
// ---------------------------------------------------------------------------
__global__ __launch_bounds__(256, 2) void o_gemm(
    const __half* __restrict__ Ctx, const __half* __restrict__ Wo,
    const float* __restrict__ bias, float* __restrict__ Out)
{
    extern __shared__ __align__(16) char sm[];
    const int tileM = blockIdx.y * BM, tileN = blockIdx.x * BN;   // swapped

    float acc[4][4][4];
    gemm_core(Ctx, Wo, tileM, tileN, sm, acc);

    const int warp = threadIdx.x >> 5, lane = threadIdx.x & 31;
    const int wm = warp >> 2, wn = warp & 3;
    #pragma unroll
    for (int mf = 0; mf < 4; mf++) {
        #pragma unroll
        for (int nf = 0; nf < 4; nf++) {
            int m0 = tileM + wm * 64 + mf * 16 + (lane >> 2);
            int n0 = tileN + wn * 32 + nf * 8 + (lane & 3) * 2;
            float bv0 = bias[n0], bv1 = bias[n0 + 1];
            *(float2*)(Out + (size_t)m0 * N + n0) =
                make_float2(acc[mf][nf][0] + bv0, acc[mf][nf][1] + bv1);
            *(float2*)(Out + (size_t)(m0 + 8) * N + n0) =
                make_float2(acc[mf][nf][2] + bv0, acc[mf][nf][3] + bv1);
        }
    }
}

// ---------------------------------------------------------------------------
// Attention (unchanged from R13): 128 threads, 4 warps x 32 q-rows.
// fp16x2 exp2, ones-row row sums via tensor pipe.
// ---------------------------------------------------------------------------
__global__ __launch_bounds__(128, 2) void attn_kernel(
    const __half* __restrict__ Q, const __half* __restrict__ Kg,
    const __half* __restrict__ Vt, __half* __restrict__ Ctx)
{
    constexpr int LDSA = 72;               // 144B stride: ldmatrix conflict-free
    constexpr int KV_STAGE_B = 64 * LDSA * 2;    // K buffer: 9216 bytes
    constexpr int V_STAGE_B  = 80 * LDSA * 2;    // V buffer incl. ones rows
    __shared__ __align__(16) __half Ks[2][64 * LDSA];   // [key][d]
    __shared__ __align__(16) __half Vs[2][80 * LDSA];   // [d][key] + ones block

    const int tid = threadIdx.x, warp = tid >> 5, lane = tid & 31;
    const int bh = blockIdx.y;
    const int qbase = blockIdx.x * 128;
    const int c0 = (lane & 3) * 2;
    const int l8 = lane & 7;
    const int bRowOff = ((lane >> 4) & 1) * 8;
    const int bColOff = ((lane >> 3) & 1) * 8;
    const __half* Qb = Q  + (size_t)bh * Pseq * D;
    const __half* Kb = Kg + (size_t)bh * Pseq * D;
    const __half* Vb = Vt + (size_t)bh * D * Pseq;

    // Q fragments: 2 m-frags x 4 k-steps
    uint32_t qf[2][4][4];
    #pragma unroll
    for (int mf = 0; mf < 2; mf++) {
        int r0 = qbase + warp * 32 + mf * 16 + (lane >> 2);
        #pragma unroll
        for (int ks = 0; ks < 4; ks++) {
            qf[mf][ks][0] = *(const uint32_t*)(Qb + (size_t)r0 * D + ks * 16 + c0);
            qf[mf][ks][1] = *(const uint32_t*)(Qb + (size_t)(r0 + 8) * D + ks * 16 + c0);
            qf[mf][ks][2] = *(const uint32_t*)(Qb + (size_t)r0 * D + ks * 16 + c0 + 8);
            qf[mf][ks][3] = *(const uint32_t*)(Qb + (size_t)(r0 + 8) * D + ks * 16 + c0 + 8);
        }
    }

    const uint32_t ksBase = smem_u32(&Ks[0][0]);
    const uint32_t vsBase = smem_u32(&Vs[0][0]);
    uint32_t rOff[5];
    #pragma unroll
    for (int np = 0; np < 5; np++) {
        int row = np * 16 + bRowOff + l8;
        rOff[np] = (uint32_t)(row * LDSA + bColOff) * 2;
    }

    // Ones-row blocks in both V buffers (cp.async only writes rows 0..63)
    for (int idx = tid; idx < 16 * 64; idx += 128) {
        int r = idx >> 6, c = idx & 63;
        __half v = (r == 0) ? __float2half(1.0f) : __float2half(0.0f);
        Vs[0][(64 + r) * LDSA + c] = v;
        Vs[1][(64 + r) * LDSA + c] = v;
    }

    float o[2][8][4];
    #pragma unroll
    for (int mf = 0; mf < 2; mf++)
        #pragma unroll
        for (int i = 0; i < 8; i++)
            #pragma unroll
            for (int r = 0; r < 4; r++) o[mf][i][r] = 0.f;
    float o9[2][4] = {};

    auto issueKV = [&](int kt, int s) {
        #pragma unroll
        for (int i = 0; i < 4; i++) {
            int idx = tid + 128 * i;
            int row = idx >> 3, grp = idx & 7;
            cp16(ksBase + (uint32_t)(row * LDSA + grp * 8) * 2 + s * KV_STAGE_B,
                 Kb + (size_t)(kt * 64 + row) * D + grp * 8);
            cp16(vsBase + (uint32_t)(row * LDSA + grp * 8) * 2 + s * V_STAGE_B,
                 Vb + (size_t)row * Pseq + kt * 64 + grp * 8);
        }
    };

    issueKV(0, 0); cp_commit();
    __syncthreads();           // ones-block init visible before first compute
    for (int kt = 0; kt < 16; kt++) {
        const int s = kt & 1;
        const uint32_t kBuf = ksBase + s * KV_STAGE_B;
        const uint32_t vBuf = vsBase + s * V_STAGE_B;
        cp_wait<0>();
        __syncthreads();
        if (kt < 15) issueKV(kt + 1, s ^ 1);
        cp_commit();

        // S = Q K^T  (32 x 64 per warp); each bf load feeds both m-frags
        float sreg[2][8][4];
        #pragma unroll
        for (int mf = 0; mf < 2; mf++)
            #pragma unroll
            for (int i = 0; i < 8; i++)
                #pragma unroll
                for (int r = 0; r < 4; r++) sreg[mf][i][r] = 0.f;
        #pragma unroll
        for (int ks = 0; ks < 4; ks++) {
            uint32_t bf[8][2];
            #pragma unroll
            for (int np = 0; np < 4; np++)
                ldsm_x4(bf[2 * np][0], bf[2 * np][1],
                        bf[2 * np + 1][0], bf[2 * np + 1][1],
                        kBuf + rOff[np] + ks * 32);
            #pragma unroll
            for (int mf = 0; mf < 2; mf++)
                #pragma unroll
                for (int nf = 0; nf < 8; nf++)
                    mma16816(sreg[mf][nf], qf[mf][ks], bf[nf]);
        }

        // softmax numerator: pack to PV A-frag layout, then fp16x2 exp2
        uint32_t pf[2][4][4];
        #pragma unroll
        for (int mf = 0; mf < 2; mf++)
            #pragma unroll
            for (int jj = 0; jj < 4; jj++) {
                pf[mf][jj][0] = h2exp2(pack_h2(sreg[mf][2 * jj][0],     sreg[mf][2 * jj][1]));
                pf[mf][jj][1] = h2exp2(pack_h2(sreg[mf][2 * jj][2],     sreg[mf][2 * jj][3]));
                pf[mf][jj][2] = h2exp2(pack_h2(sreg[mf][2 * jj + 1][0], sreg[mf][2 * jj + 1][1]));
                pf[mf][jj][3] = h2exp2(pack_h2(sreg[mf][2 * jj + 1][2], sreg[mf][2 * jj + 1][3]));
            }

        // O += P V ; 9th n-frag (ones row) accumulates row sums
        #pragma unroll
        for (int jj = 0; jj < 4; jj++) {
            uint32_t bf[8][2], b9[4];
            #pragma unroll
            for (int np = 0; np < 4; np++)
                ldsm_x4(bf[2 * np][0], bf[2 * np][1],
                        bf[2 * np + 1][0], bf[2 * np + 1][1],
                        vBuf + rOff[np] + jj * 32);
            ldsm_x4(b9[0], b9[1], b9[2], b9[3], vBuf + rOff[4] + jj * 32);
            #pragma unroll
            for (int mf = 0; mf < 2; mf++) {
                #pragma unroll
                for (int nf = 0; nf < 8; nf++)
                    mma16816(o[mf][nf], pf[mf][jj], bf[nf]);
                mma16816(o9[mf], pf[mf][jj], b9);
            }
        }
    }

    const int b0 = bh >> 4, h0 = bh & 15;
    const size_t obase = (size_t)b0 * Pseq * E + (size_t)h0 * D;
    #pragma unroll
    for (int mf = 0; mf < 2; mf++) {
        const float rin0 = 1.f / __shfl_sync(0xffffffffu, o9[mf][0], 0, 4);
        const float rin1 = 1.f / __shfl_sync(0xffffffffu, o9[mf][2], 0, 4);
        const int prow = qbase + warp * 32 + mf * 16 + (lane >> 2);
        #pragma unroll
        for (int nf = 0; nf < 8; nf++) {
            int d0 = nf * 8 + c0;
            *(__half2*)(Ctx + obase + (size_t)prow * E + d0) =
                __floats2half2_rn(o[mf][nf][0] * rin0, o[mf][nf][1] * rin0);
            *(__half2*)(Ctx + obase + (size_t)(prow + 8) * E + d0) =
                __floats2half2_rn(o[mf][nf][2] * rin1, o[mf][nf][3] * rin1);
        }
    }
}

// ---------------------------------------------------------------------------
extern "C" void kernel_launch(void* const* d_in, const int* in_sizes, int n_in,
                              void* d_out, int out_size)
{
    const float* x  = (const float*)d_in[0];
    const float* wq = (const float*)d_in[1];
    const float* bq = (const float*)d_in[2];
    const float* wk = (const float*)d_in[3];
    const float* bk = (const float*)d_in[4];
    const float* wv = (const float*)d_in[5];
    const float* bv = (const float*)d_in[6];
    const float* wo = (const float*)d_in[7];
    const float* bo = (const float*)d_in[8];

    void *pxh, *pw4, *pq, *pk, *pv, *pc;
    cudaGetSymbolAddress(&pxh, g_xh);
    cudaGetSymbolAddress(&pw4, g_w4);
    cudaGetSymbolAddress(&pq, g_q);
    cudaGetSymbolAddress(&pk, g_k);
    cudaGetSymbolAddress(&pv, g_vt);
    cudaGetSymbolAddress(&pc, g_ctx);

    __half* xh = (__half*)pxh;
    __half* w4 = (__half*)pw4;

    cudaFuncSetAttribute(qkv_gemm, cudaFuncAttributeMaxDynamicSharedMemorySize,
                         GEMM_SMEM);
    cudaFuncSetAttribute(o_gemm, cudaFuncAttributeMaxDynamicSharedMemorySize,
                         GEMM_SMEM);

    // Pre-convert inputs to fp16
    cvt_kernel<<<1024, 256>>>(x, xh, M * E / 4);
    wcvt_kernel<<<dim3(128, 4), 256>>>(wq, wk, wv, wo, w4);

    // Swapped grid: x = N-tiles (8), y = M-tiles (128) -> A reused in L2
    dim3 gq(N / BN, M / BM, 3);
    qkv_gemm<<<gq, 256, GEMM_SMEM>>>(xh, w4, bq, bk, bv,
                                     (__half*)pq, (__half*)pk, (__half*)pv);
    attn_kernel<<<dim3(8, 256), 128>>>((const __half*)pq, (const __half*)pk,
                                       (const __half*)pv, (__half*)pc);
    o_gemm<<<dim3(N / BN, M / BM), 256, GEMM_SMEM>>>((const __half*)pc,
                                                     w4 + 3 * (size_t)E * E, bo,
                                                     (float*)d_out);
}